// round 8
// baseline (speedup 1.0000x reference)
#include <cuda_runtime.h>
#include <cuda_fp16.h>
#include <cstdint>

// ---------------- problem constants ----------------
#define N_INPUT   1024
#define N_OUTPUT  512
#define BATCHC    32
#define T_STEPS   100
#define TB_PAD    104                    // padded per-b t-length
#define K_PAD     (BATCHC * TB_PAD)      // 3328
#define K_SPLIT   2
#define K_PART    (K_PAD / K_SPLIT)      // 1664
#define CHUNK     64                     // k per pipeline stage
#define NCHUNKS   (K_PART / CHUNK)       // 26

#define SEG_LEN   26                     // 4 segments of 26 (incl. 4 pads)
#define DECAY     (0.951229424500714f)   // exp(-1/20)
#define D26       (0.272531793034013f)   // exp(-26/20)

#define LR_LTP_F  (1e-4f)
#define LR_LTD_F  (-1e-4f)

#define PRETR_OFF  (N_OUTPUT * N_INPUT)
#define POSTTR_OFF (PRETR_OFF + BATCHC * N_INPUT)

// ---------------- device scratch (no allocations) ----------------
static __device__ __align__(16) __half g_A0[N_OUTPUT * K_PAD]; // postS  [o][k]
static __device__ __align__(16) __half g_A1[N_OUTPUT * K_PAD]; // postTr [o][k]
static __device__ __align__(16) __half g_B0[N_INPUT  * K_PAD]; // preTr  [i][k]
static __device__ __align__(16) __half g_B1[N_INPUT  * K_PAD]; // preS   [i][k]
static __device__ float g_P0[K_SPLIT * N_OUTPUT * N_INPUT];    // ltp partials
static __device__ float g_P1[K_SPLIT * N_OUTPUT * N_INPUT];    // ltd partials

// ---------------- helpers ----------------
__device__ __forceinline__ uint32_t smem_u32(const void* p) {
    uint32_t a;
    asm("{ .reg .u64 t; cvta.to.shared.u64 t, %1; cvt.u32.u64 %0, t; }"
        : "=r"(a) : "l"(p));
    return a;
}
__device__ __forceinline__ void bulk_g2s(uint32_t dst, const void* src,
                                         uint32_t bytes, uint32_t mbar) {
    asm volatile(
        "cp.async.bulk.shared::cluster.global.mbarrier::complete_tx::bytes "
        "[%0], [%1], %2, [%3];"
        :: "r"(dst), "l"(src), "r"(bytes), "r"(mbar) : "memory");
}
#define MBARRIER_INIT(addr, cnt) \
    asm volatile("mbarrier.init.shared.b64 [%0], %1;" \
                 :: "r"((uint32_t)(addr)), "r"((uint32_t)(cnt)) : "memory")
#define MBARRIER_EXPECT_TX(addr, bytes) \
    asm volatile("mbarrier.arrive.expect_tx.shared.b64 _, [%0], %1;" \
                 :: "r"((uint32_t)(addr)), "r"((uint32_t)(bytes)) : "memory")
#define MBARRIER_WAIT_PARITY(addr, par) do {                                   \
    uint32_t _m = (uint32_t)(addr), _p = (uint32_t)(par), _d;                  \
    asm volatile("{\n\t.reg .pred p;\n\t"                                      \
        "mbarrier.try_wait.parity.acquire.cta.shared::cta.b64 p, [%1], %2;\n\t"\
        "selp.b32 %0, 1, 0, p;\n\t}" : "=r"(_d) : "r"(_m), "r"(_p) : "memory");\
    if (!_d) {                                                                 \
        asm volatile("{\n\t.reg .pred P1;\n\t"                                 \
        "WL_%=:\n\t"                                                           \
        "mbarrier.try_wait.parity.acquire.cta.shared::cta.b64 P1, [%0], %1, 0x989680;\n\t" \
        "@P1 bra.uni WD_%=;\n\t"                                               \
        "bra.uni WL_%=;\n\t"                                                   \
        "WD_%=:\n\t}" :: "r"(_m), "r"(_p) : "memory");                         \
    }                                                                          \
} while (0)

__device__ __forceinline__ void ldm_x4(uint32_t* r, uint32_t addr) {
    asm volatile("ldmatrix.sync.aligned.m8n8.x4.shared.b16 {%0,%1,%2,%3}, [%4];"
                 : "=r"(r[0]), "=r"(r[1]), "=r"(r[2]), "=r"(r[3]) : "r"(addr));
}
__device__ __forceinline__ void mma16816(float* c, const uint32_t* a,
                                         uint32_t b0, uint32_t b1) {
    asm volatile(
        "mma.sync.aligned.m16n8k16.row.col.f32.f16.f16.f32 "
        "{%0,%1,%2,%3}, {%4,%5,%6,%7}, {%8,%9}, {%0,%1,%2,%3};"
        : "+f"(c[0]), "+f"(c[1]), "+f"(c[2]), "+f"(c[3])
        : "r"(a[0]), "r"(a[1]), "r"(a[2]), "r"(a[3]), "r"(b0), "r"(b1));
}

// ===========================================================================
// Kernel 1: prep — 4-way segmented trace scan + spike fp16 K-major transpose.
// Thread = (b, col, seg). Segment = 26 t-steps (t >= 100 are zero pads).
// 4 segs of one (b,col) sit on consecutive lanes; carries via shfl.
// Grid 768 CTAs x 256 = 196608 threads = 49152 groups x 4 segs.
// ===========================================================================
__global__ void __launch_bounds__(256) prep_kernel(
    const float* __restrict__ pre_s,    // [100][32][1024]
    const float* __restrict__ post_s,   // [100][32][512]
    const float* __restrict__ pre_tr0,
    const float* __restrict__ post_tr0,
    float* __restrict__ out)
{
    const int idx  = blockIdx.x * 256 + threadIdx.x;
    const int lane = threadIdx.x & 31;
    const int seg  = idx & 3;
    const int grp  = idx >> 2;               // (b, col), 0..49151

    const float *src, *tr0p;
    __half *trd, *spd;
    int b, col, nc, trout;
    if (grp < 32768) {                        // pre side
        b = grp >> 10; col = grp & 1023; nc = N_INPUT;
        src = pre_s; tr0p = pre_tr0; trd = g_B0; spd = g_B1;
        trout = PRETR_OFF + b * N_INPUT + col;
    } else {                                  // post side
        int g2 = grp - 32768;
        b = g2 >> 9; col = g2 & 511; nc = N_OUTPUT;
        src = post_s; tr0p = post_tr0; trd = g_A1; spd = g_A0;
        trout = POSTTR_OFF + b * N_OUTPUT + col;
    }
    const int base = b * nc + col;           // index within one t-slice
    const int t0   = seg * SEG_LEN;
    const size_t rowoff = (size_t)col * K_PAD + b * TB_PAD + t0;

    // partial scan from 0 over this segment; store spike fp16 on the fly
    float pv[SEG_LEN];
    float p = 0.f;
    #pragma unroll
    for (int i = 0; i < SEG_LEN; i += 2) {
        float v0 = (t0 + i     < T_STEPS) ? src[(size_t)(t0 + i)     * (BATCHC * nc) + base] : 0.f;
        float v1 = (t0 + i + 1 < T_STEPS) ? src[(size_t)(t0 + i + 1) * (BATCHC * nc) + base] : 0.f;
        p = p * DECAY + v0; pv[i] = p;
        p = p * DECAY + v1; pv[i + 1] = p;
        __half2 h = __halves2half2(__float2half(v0), __float2half(v1));
        *(uint32_t*)(spd + rowoff + i) = *(uint32_t*)&h;
    }

    // carries: E = trace value entering this segment
    const float P   = p;
    const int   bl  = lane & ~3;
    const float P0  = __shfl_sync(0xffffffffu, P, bl + 0);
    const float P1  = __shfl_sync(0xffffffffu, P, bl + 1);
    const float P2  = __shfl_sync(0xffffffffu, P, bl + 2);
    float E = tr0p[base];
    if (seg > 0) E = E * D26 + P0;
    if (seg > 1) E = E * D26 + P1;
    if (seg > 2) E = E * D26 + P2;

    // corrected traces: tr[t0+i] = pv[i] + E * DECAY^(i+1)
    float f = E * DECAY;
    float fin = 0.f;
    #pragma unroll
    for (int i = 0; i < SEG_LEN; i += 2) {
        float tv0 = pv[i] + f;     f *= DECAY;
        float tv1 = pv[i + 1] + f; f *= DECAY;
        if (i == 20) fin = tv1;                       // t = 78 + 21 = 99
        __half2 h = __halves2half2(__float2half(tv0), __float2half(tv1));
        *(uint32_t*)(trd + rowoff + i) = *(uint32_t*)&h;
    }
    if (seg == 3) out[trout] = fin;
}

// ===========================================================================
// Kernel 2: dual fp16 GEMM via mma.sync; cp.async.bulk (128B rows) + mbarrier,
// 3-stage pipeline. grid = (32 tiles, 4): y&1 = gemm id, y>>1 = k-split.
// 256 threads, 8 warps as 4(m)x2(n), warp tile 32x64, CTA tile 128x128.
// ===========================================================================
#define PITCH       144                  // bytes per smem row (72 halves)
#define A_STAGE     (128 * PITCH)        // 18432
#define STAGE_BYTES (2 * A_STAGE)        // 36864
#define MB_OFF      (3 * STAGE_BYTES)    // 110592
#define GSMEM_TOTAL (MB_OFF + 64)
#define STAGE_TX    32768                // payload bytes per stage (2*128*128)

__global__ void __launch_bounds__(256, 1) gemm_kernel()
{
    extern __shared__ __align__(128) char smem[];
    const uint32_t sb = smem_u32(smem);
    const int tid = threadIdx.x, lane = tid & 31, wid = tid >> 5;
    const int mt = blockIdx.x & 3, ntb = blockIdx.x >> 2;
    const int gsel = blockIdx.y & 1, ks = blockIdx.y >> 1;

    const __half* Ag = gsel ? g_A1 : g_A0;
    const __half* Bg = gsel ? g_B1 : g_B0;
    float* Pg = gsel ? g_P1 : g_P0;
    const size_t kbase = (size_t)ks * K_PART;
    const __half* Arow = Ag + (size_t)(mt * 128) * K_PAD + kbase;
    const __half* Brow = Bg + (size_t)(ntb * 128) * K_PAD + kbase;

    if (tid == 0) {
        MBARRIER_INIT(sb + MB_OFF + 0,  1);
        MBARRIER_INIT(sb + MB_OFF + 8,  1);
        MBARRIER_INIT(sb + MB_OFF + 16, 1);
    }
    __syncthreads();

    // warp-0 stage issue: 256 x 128B bulk copies + expect_tx
    auto issue_stage = [&](int c) {
        const int s = c % 3;
        const uint32_t mb  = sb + MB_OFF + s * 8;
        const uint32_t buf = sb + s * STAGE_BYTES;
        if (lane == 0) MBARRIER_EXPECT_TX(mb, STAGE_TX);
        __syncwarp();
        #pragma unroll
        for (int j = 0; j < 8; j++) {
            int o   = j * 32 + lane;             // 0..255
            int row = o & 127, isB = o >> 7;
            const __half* s0 = (isB ? Brow : Arow) + (size_t)row * K_PAD + c * CHUNK;
            bulk_g2s(buf + isB * A_STAGE + row * PITCH, s0, 128, mb);
        }
    };

    if (wid == 0) { issue_stage(0); issue_stage(1); issue_stage(2); }

    float acc[2][8][4];
    #pragma unroll
    for (int i = 0; i < 2; i++)
        #pragma unroll
        for (int j = 0; j < 8; j++)
            #pragma unroll
            for (int r = 0; r < 4; r++) acc[i][j][r] = 0.f;

    const int m_base = (wid >> 1) * 32;
    const int n_base = (wid & 1) * 64;
    const uint32_t aoff = (uint32_t)((m_base + (lane & 15)) * PITCH
                                     + (lane >> 4) * 16);
    const uint32_t boff = (uint32_t)(A_STAGE
                          + (n_base + ((lane >> 4) << 3) + (lane & 7)) * PITCH
                          + ((lane >> 3) & 1) * 16);

    for (int c = 0; c < NCHUNKS; c++) {
        MBARRIER_WAIT_PARITY(sb + MB_OFF + (c % 3) * 8, (c / 3) & 1);

        const uint32_t buf = sb + (c % 3) * STAGE_BYTES;
        #pragma unroll
        for (int kk = 0; kk < 4; kk++) {
            const uint32_t k0b = kk * 32;
            uint32_t ra[2][4], rb[4][4];
            #pragma unroll
            for (int mtt = 0; mtt < 2; mtt++)
                ldm_x4(ra[mtt], buf + aoff + mtt * (16 * PITCH) + k0b);
            #pragma unroll
            for (int np = 0; np < 4; np++)
                ldm_x4(rb[np], buf + boff + np * (16 * PITCH) + k0b);
            #pragma unroll
            for (int mtt = 0; mtt < 2; mtt++)
                #pragma unroll
                for (int ntt = 0; ntt < 8; ntt++)
                    mma16816(acc[mtt][ntt], ra[mtt],
                             rb[ntt >> 1][(ntt & 1) * 2],
                             rb[ntt >> 1][(ntt & 1) * 2 + 1]);
        }
        __syncthreads();                       // all warps done reading stage
        if (wid == 0 && c + 3 < NCHUNKS) issue_stage(c + 3);
    }

    // epilogue: fp32 partials
    const int gid = lane >> 2, tig = lane & 3;
    #pragma unroll
    for (int mtt = 0; mtt < 2; mtt++) {
        #pragma unroll
        for (int ntt = 0; ntt < 8; ntt++) {
            int m = mt * 128 + m_base + mtt * 16 + gid;
            int n = ntb * 128 + n_base + ntt * 8 + 2 * tig;
            float* d0 = Pg + ((size_t)ks * N_OUTPUT + m) * N_INPUT + n;
            float* d1 = Pg + ((size_t)ks * N_OUTPUT + m + 8) * N_INPUT + n;
            float2 v0; v0.x = acc[mtt][ntt][0]; v0.y = acc[mtt][ntt][1];
            float2 v1; v1.x = acc[mtt][ntt][2]; v1.y = acc[mtt][ntt][3];
            *(float2*)d0 = v0;
            *(float2*)d1 = v1;
        }
    }
}

// ===========================================================================
// Kernel 3: reduce split-K partials + soft bounds -> dw
// ===========================================================================
__global__ void __launch_bounds__(256) reduce_kernel(
    const float* __restrict__ W, float* __restrict__ dw)
{
    const int o = blockIdx.x, t = threadIdx.x;
    const size_t ro = (size_t)o * (N_INPUT / 4) + t;
    float4 s0 = make_float4(0.f, 0.f, 0.f, 0.f);
    float4 s1 = make_float4(0.f, 0.f, 0.f, 0.f);
    #pragma unroll
    for (int p = 0; p < K_SPLIT; p++) {
        float4 a = ((const float4*)g_P0)[(size_t)p * (N_OUTPUT * N_INPUT / 4) + ro];
        float4 b = ((const float4*)g_P1)[(size_t)p * (N_OUTPUT * N_INPUT / 4) + ro];
        s0.x += a.x; s0.y += a.y; s0.z += a.z; s0.w += a.w;
        s1.x += b.x; s1.y += b.y; s1.z += b.z; s1.w += b.w;
    }
    const float c1 = LR_LTP_F / (float)BATCHC;
    const float c2 = LR_LTD_F / (float)BATCHC;
    float4 w4 = ((const float4*)W)[ro];
    float4 r;
    r.x = c1 * (1.f - w4.x) * s0.x + c2 * w4.x * s1.x;
    r.y = c1 * (1.f - w4.y) * s0.y + c2 * w4.y * s1.y;
    r.z = c1 * (1.f - w4.z) * s0.z + c2 * w4.z * s1.z;
    r.w = c1 * (1.f - w4.w) * s0.w + c2 * w4.w * s1.w;
    ((float4*)dw)[ro] = r;
}

// ===========================================================================
extern "C" void kernel_launch(void* const* d_in, const int* in_sizes, int n_in,
                              void* d_out, int out_size)
{
    const float* W        = (const float*)d_in[0];
    const float* pre_s    = (const float*)d_in[1];
    const float* post_s   = (const float*)d_in[2];
    const float* pre_tr0  = (const float*)d_in[3];
    const float* post_tr0 = (const float*)d_in[4];
    float* out = (float*)d_out;
    (void)in_sizes; (void)n_in; (void)out_size;

    cudaFuncSetAttribute(gemm_kernel,
                         cudaFuncAttributeMaxDynamicSharedMemorySize, GSMEM_TOTAL);

    prep_kernel<<<768, 256>>>(pre_s, post_s, pre_tr0, post_tr0, out);
    gemm_kernel<<<dim3(32, 4), 256, GSMEM_TOTAL>>>();
    reduce_kernel<<<N_OUTPUT, 256>>>(W, out);
}

// round 13
// speedup vs baseline: 5.4873x; 5.4873x over previous
#include <cuda_runtime.h>
#include <cuda_fp16.h>
#include <cstdint>

// ---------------- problem constants ----------------
#define N_INPUT   1024
#define N_OUTPUT  512
#define BATCHC    32
#define T_STEPS   100
#define TB_PAD    104                    // padded per-b t-length
#define K_PAD     (BATCHC * TB_PAD)      // 3328
#define K_SPLIT   2
#define K_PART    (K_PAD / K_SPLIT)      // 1664
#define CHUNK     64                     // k per pipeline stage
#define NCHUNKS   (K_PART / CHUNK)       // 26

#define SEG_LEN   26                     // 4 segments of 26 (incl. 4 pads)
#define DECAY     (0.951229424500714f)   // exp(-1/20)
#define D26       (0.272531793034013f)   // exp(-26/20)

#define LR_LTP_F  (1e-4f)
#define LR_LTD_F  (-1e-4f)

#define PRETR_OFF  (N_OUTPUT * N_INPUT)
#define POSTTR_OFF (PRETR_OFF + BATCHC * N_INPUT)

// ---------------- device scratch (no allocations) ----------------
static __device__ __align__(16) __half g_A0[N_OUTPUT * K_PAD]; // postS  [o][k]
static __device__ __align__(16) __half g_A1[N_OUTPUT * K_PAD]; // postTr [o][k]
static __device__ __align__(16) __half g_B0[N_INPUT  * K_PAD]; // preTr  [i][k]
static __device__ __align__(16) __half g_B1[N_INPUT  * K_PAD]; // preS   [i][k]
static __device__ float g_P0[K_SPLIT * N_OUTPUT * N_INPUT];    // ltp partials
static __device__ float g_P1[K_SPLIT * N_OUTPUT * N_INPUT];    // ltd partials

// ---------------- helpers ----------------
__device__ __forceinline__ uint32_t smem_u32(const void* p) {
    uint32_t a;
    asm("{ .reg .u64 t; cvta.to.shared.u64 t, %1; cvt.u32.u64 %0, t; }"
        : "=r"(a) : "l"(p));
    return a;
}
__device__ __forceinline__ void cp_async16(uint32_t dst, const void* src) {
    asm volatile("cp.async.cg.shared.global [%0], [%1], 16;"
                 :: "r"(dst), "l"(src) : "memory");
}
#define CP_COMMIT() asm volatile("cp.async.commit_group;" ::: "memory")
#define CP_WAIT1()  asm volatile("cp.async.wait_group 1;" ::: "memory")

__device__ __forceinline__ void ldm_x4(uint32_t* r, uint32_t addr) {
    asm volatile("ldmatrix.sync.aligned.m8n8.x4.shared.b16 {%0,%1,%2,%3}, [%4];"
                 : "=r"(r[0]), "=r"(r[1]), "=r"(r[2]), "=r"(r[3]) : "r"(addr));
}
__device__ __forceinline__ void mma16816(float* c, const uint32_t* a,
                                         uint32_t b0, uint32_t b1) {
    asm volatile(
        "mma.sync.aligned.m16n8k16.row.col.f32.f16.f16.f32 "
        "{%0,%1,%2,%3}, {%4,%5,%6,%7}, {%8,%9}, {%0,%1,%2,%3};"
        : "+f"(c[0]), "+f"(c[1]), "+f"(c[2]), "+f"(c[3])
        : "r"(a[0]), "r"(a[1]), "r"(a[2]), "r"(a[3]), "r"(b0), "r"(b1));
}

// ===========================================================================
// Kernel 1: prep — segmented trace scan + fp16 K-major transpose, fully
// coalesced. CTA = (b, 64 cols); warp = 32 consecutive cols of one segment.
// Carries via smem; fp16 output staged in smem, copied out row-contiguous.
// Grid: 512 pre-CTAs (32 b x 16 colgrps) + 256 post-CTAs (32 b x 8) = 768.
// ===========================================================================
__global__ void __launch_bounds__(256) prep_kernel(
    const float* __restrict__ pre_s,    // [100][32][1024]
    const float* __restrict__ post_s,   // [100][32][512]
    const float* __restrict__ pre_tr0,
    const float* __restrict__ post_tr0,
    float* __restrict__ out)
{
    __shared__ uint32_t s_sp[64][53];   // spike fp16 pairs, word = k/2
    __shared__ uint32_t s_tr[64][53];   // trace fp16 pairs
    __shared__ float    s_P[4][64];     // per-seg partial-scan end values

    const int bx = blockIdx.x, tid = threadIdx.x;
    const int w = tid >> 5, lane = tid & 31;
    const int seg = w >> 1;                         // 0..3
    const int colL = (w & 1) * 32 + lane;           // 0..63

    const float *src, *tr0p;
    __half *trd, *spd;
    int b, col0, nc, outbase;
    if (bx < 512) {                                 // pre side
        b = bx >> 4; col0 = (bx & 15) * 64; nc = N_INPUT;
        src = pre_s; tr0p = pre_tr0; trd = g_B0; spd = g_B1;
        outbase = PRETR_OFF + b * N_INPUT;
    } else {                                        // post side
        int e = bx - 512;
        b = e >> 3; col0 = (e & 7) * 64; nc = N_OUTPUT;
        src = post_s; tr0p = post_tr0; trd = g_A1; spd = g_A0;
        outbase = POSTTR_OFF + b * N_OUTPUT;
    }
    const int col = col0 + colL;
    const int srcbase = b * nc + col;               // index within one t-slice
    const int t0 = seg * SEG_LEN;

    // pass 1: partial scan from 0; spike fp16 pairs -> smem staging
    float pv[SEG_LEN];
    float p = 0.f;
    #pragma unroll
    for (int i = 0; i < SEG_LEN; i += 2) {
        float v0 = (t0 + i     < T_STEPS) ? src[(size_t)(t0 + i)     * (BATCHC * nc) + srcbase] : 0.f;
        float v1 = (t0 + i + 1 < T_STEPS) ? src[(size_t)(t0 + i + 1) * (BATCHC * nc) + srcbase] : 0.f;
        p = p * DECAY + v0; pv[i] = p;
        p = p * DECAY + v1; pv[i + 1] = p;
        __half2 h = __halves2half2(__float2half(v0), __float2half(v1));
        s_sp[colL][seg * 13 + (i >> 1)] = *(uint32_t*)&h;
    }
    s_P[seg][colL] = p;
    __syncthreads();

    // carry: E = trace entering this segment (identical formula to round 8)
    float E = tr0p[srcbase];
    if (seg > 0) E = E * D26 + s_P[0][colL];
    if (seg > 1) E = E * D26 + s_P[1][colL];
    if (seg > 2) E = E * D26 + s_P[2][colL];

    // pass 2: corrected traces -> smem staging
    float f = E * DECAY;
    float fin = 0.f;
    #pragma unroll
    for (int i = 0; i < SEG_LEN; i += 2) {
        float tv0 = pv[i] + f;     f *= DECAY;
        float tv1 = pv[i + 1] + f; f *= DECAY;
        if (i == 20) fin = tv1;                     // t = 78 + 21 = 99
        __half2 h = __halves2half2(__float2half(tv0), __float2half(tv1));
        s_tr[colL][seg * 13 + (i >> 1)] = *(uint32_t*)&h;
    }
    __syncthreads();

    // coalesced copy-out: 64 rows x 52 words each, row-contiguous
    uint32_t* sp32 = (uint32_t*)spd;
    uint32_t* tr32 = (uint32_t*)trd;
    const int wbase = b * (TB_PAD / 2);             // word offset within row
    #pragma unroll
    for (int it = 0; it < 13; it++) {
        int idx = it * 256 + tid;                   // 0..3327
        int rowL = idx / 52, e = idx - rowL * 52;
        size_t g = (size_t)(col0 + rowL) * (K_PAD / 2) + wbase + e;
        sp32[g] = s_sp[rowL][e];
        tr32[g] = s_tr[rowL][e];
    }

    if (seg == 3) out[outbase + col] = fin;
}

// ===========================================================================
// Kernel 2: dual fp16 GEMM via mma.sync, 3-stage cp.async pipeline.
// (verbatim round-4 version — measured at the legacy-HMMA floor)
// grid = (32 tiles, 4): y&1 = gemm id, y>>1 = k-split. 256 threads, 8 warps
// as 4(m)x2(n), warp tile 32x64, CTA tile 128x128.
// ===========================================================================
#define PITCH       144                  // bytes per smem row (72 halves)
#define A_STAGE     (128 * PITCH)        // 18432
#define STAGE_BYTES (2 * A_STAGE)        // 36864
#define GSMEM_TOTAL (3 * STAGE_BYTES)    // 110592

__global__ void __launch_bounds__(256, 1) gemm_kernel()
{
    extern __shared__ __align__(128) char smem[];
    const uint32_t sb = smem_u32(smem);
    const int tid = threadIdx.x, lane = tid & 31, wid = tid >> 5;
    const int mt = blockIdx.x & 3, ntb = blockIdx.x >> 2;
    const int gsel = blockIdx.y & 1, ks = blockIdx.y >> 1;

    const __half* Ag = gsel ? g_A1 : g_A0;
    const __half* Bg = gsel ? g_B1 : g_B0;
    float* Pg = gsel ? g_P1 : g_P0;
    const size_t kbase = (size_t)ks * K_PART;
    const __half* Arow = Ag + (size_t)(mt * 128) * K_PAD + kbase;
    const __half* Brow = Bg + (size_t)(ntb * 128) * K_PAD + kbase;

    auto load_stage = [&](int c) {
        const uint32_t buf = sb + (c % 3) * STAGE_BYTES;
        #pragma unroll
        for (int it = 0; it < 4; it++) {
            int slot = it * 256 + tid;          // 0..1023
            int row = slot >> 3, sub = slot & 7;
            cp_async16(buf + row * PITCH + sub * 16,
                       Arow + (size_t)row * K_PAD + c * CHUNK + sub * 8);
        }
        #pragma unroll
        for (int it = 0; it < 4; it++) {
            int slot = it * 256 + tid;
            int row = slot >> 3, sub = slot & 7;
            cp_async16(buf + A_STAGE + row * PITCH + sub * 16,
                       Brow + (size_t)row * K_PAD + c * CHUNK + sub * 8);
        }
        CP_COMMIT();
    };

    float acc[2][8][4];
    #pragma unroll
    for (int i = 0; i < 2; i++)
        #pragma unroll
        for (int j = 0; j < 8; j++)
            #pragma unroll
            for (int r = 0; r < 4; r++) acc[i][j][r] = 0.f;

    const int m_base = (wid >> 1) * 32;
    const int n_base = (wid & 1) * 64;
    const uint32_t aoff = (uint32_t)((m_base + (lane & 15)) * PITCH
                                     + (lane >> 4) * 16);
    const uint32_t boff = (uint32_t)(A_STAGE
                          + (n_base + ((lane >> 4) << 3) + (lane & 7)) * PITCH
                          + ((lane >> 3) & 1) * 16);

    load_stage(0);
    load_stage(1);

    for (int c = 0; c < NCHUNKS; c++) {
        CP_WAIT1();
        __syncthreads();
        if (c + 2 < NCHUNKS) load_stage(c + 2); else CP_COMMIT();

        const uint32_t buf = sb + (c % 3) * STAGE_BYTES;
        #pragma unroll
        for (int kk = 0; kk < 4; kk++) {
            const uint32_t k0b = kk * 32;
            uint32_t ra[2][4], rb[4][4];
            #pragma unroll
            for (int mtt = 0; mtt < 2; mtt++)
                ldm_x4(ra[mtt], buf + aoff + mtt * (16 * PITCH) + k0b);
            #pragma unroll
            for (int np = 0; np < 4; np++)
                ldm_x4(rb[np], buf + boff + np * (16 * PITCH) + k0b);
            #pragma unroll
            for (int mtt = 0; mtt < 2; mtt++)
                #pragma unroll
                for (int ntt = 0; ntt < 8; ntt++)
                    mma16816(acc[mtt][ntt], ra[mtt],
                             rb[ntt >> 1][(ntt & 1) * 2],
                             rb[ntt >> 1][(ntt & 1) * 2 + 1]);
        }
    }

    const int gid = lane >> 2, tig = lane & 3;
    #pragma unroll
    for (int mtt = 0; mtt < 2; mtt++) {
        #pragma unroll
        for (int ntt = 0; ntt < 8; ntt++) {
            int m = mt * 128 + m_base + mtt * 16 + gid;
            int n = ntb * 128 + n_base + ntt * 8 + 2 * tig;
            float* d0 = Pg + ((size_t)ks * N_OUTPUT + m) * N_INPUT + n;
            float* d1 = Pg + ((size_t)ks * N_OUTPUT + m + 8) * N_INPUT + n;
            float2 v0; v0.x = acc[mtt][ntt][0]; v0.y = acc[mtt][ntt][1];
            float2 v1; v1.x = acc[mtt][ntt][2]; v1.y = acc[mtt][ntt][3];
            *(float2*)d0 = v0;
            *(float2*)d1 = v1;
        }
    }
}

// ===========================================================================
// Kernel 3: reduce split-K partials + soft bounds -> dw
// ===========================================================================
__global__ void __launch_bounds__(256) reduce_kernel(
    const float* __restrict__ W, float* __restrict__ dw)
{
    const int o = blockIdx.x, t = threadIdx.x;
    const size_t ro = (size_t)o * (N_INPUT / 4) + t;
    float4 s0 = make_float4(0.f, 0.f, 0.f, 0.f);
    float4 s1 = make_float4(0.f, 0.f, 0.f, 0.f);
    #pragma unroll
    for (int p = 0; p < K_SPLIT; p++) {
        float4 a = ((const float4*)g_P0)[(size_t)p * (N_OUTPUT * N_INPUT / 4) + ro];
        float4 b = ((const float4*)g_P1)[(size_t)p * (N_OUTPUT * N_INPUT / 4) + ro];
        s0.x += a.x; s0.y += a.y; s0.z += a.z; s0.w += a.w;
        s1.x += b.x; s1.y += b.y; s1.z += b.z; s1.w += b.w;
    }
    const float c1 = LR_LTP_F / (float)BATCHC;
    const float c2 = LR_LTD_F / (float)BATCHC;
    float4 w4 = ((const float4*)W)[ro];
    float4 r;
    r.x = c1 * (1.f - w4.x) * s0.x + c2 * w4.x * s1.x;
    r.y = c1 * (1.f - w4.y) * s0.y + c2 * w4.y * s1.y;
    r.z = c1 * (1.f - w4.z) * s0.z + c2 * w4.z * s1.z;
    r.w = c1 * (1.f - w4.w) * s0.w + c2 * w4.w * s1.w;
    ((float4*)dw)[ro] = r;
}

// ===========================================================================
extern "C" void kernel_launch(void* const* d_in, const int* in_sizes, int n_in,
                              void* d_out, int out_size)
{
    const float* W        = (const float*)d_in[0];
    const float* pre_s    = (const float*)d_in[1];
    const float* post_s   = (const float*)d_in[2];
    const float* pre_tr0  = (const float*)d_in[3];
    const float* post_tr0 = (const float*)d_in[4];
    float* out = (float*)d_out;
    (void)in_sizes; (void)n_in; (void)out_size;

    cudaFuncSetAttribute(gemm_kernel,
                         cudaFuncAttributeMaxDynamicSharedMemorySize, GSMEM_TOTAL);

    prep_kernel<<<768, 256>>>(pre_s, post_s, pre_tr0, post_tr0, out);
    gemm_kernel<<<dim3(32, 4), 256, GSMEM_TOTAL>>>();
    reduce_kernel<<<N_OUTPUT, 256>>>(W, out);
}